// round 11
// baseline (speedup 1.0000x reference)
#include <cuda_runtime.h>
#include <cuda_bf16.h>

#define EMB 64
#define MAXN 100000
#define MAXE 1000000
#define NLAYER 4

// ---------------- scratch (__device__ globals: allocation-free) ----------------
__device__ float g_h[(size_t)MAXN * 64];          // current node features (raw, pre-affine)
__device__ float g_agg[(size_t)MAXN * 64];        // aggregation result
__device__ float g_y[(size_t)MAXN * 128];         // GEMM1 output
__device__ float g_stats[384];                    // [sum128, sq128, sum64, sq64] (BSS zero)
__device__ float g_aff1[256];                     // BN1 affine: a[128], c[128]
__device__ float g_aff2[128];                     // outer BN affine: a[64], c[64]
// CSR build scratch (all re-established every call; g_deg zeroed by scanC)
__device__ int  g_deg[MAXN];
__device__ int  g_rowptr[MAXN + 1];
__device__ int  g_part[512];
__device__ int  g_cursor[MAXN];
__device__ int2 g_edge[MAXE];                     // {src, b0|b1<<8|b2<<16}

// ---------------- f32x2 packed-FMA helpers (sm_103a) ----------------------------
__device__ __forceinline__ void ffma2(unsigned long long& d, unsigned long long a,
                                      unsigned long long b) {
    asm("fma.rn.f32x2 %0, %1, %2, %0;" : "+l"(d) : "l"(a), "l"(b));
}
__device__ __forceinline__ unsigned long long bcast2(float v) {
    unsigned long long r;
    asm("mov.b64 %0, {%1, %1};" : "=l"(r) : "f"(v));
    return r;
}
__device__ __forceinline__ float2 unpack2(unsigned long long v) {
    float2 r;
    asm("mov.b64 {%0, %1}, %2;" : "=f"(r.x), "=f"(r.y) : "l"(v));
    return r;
}
__device__ __forceinline__ float warp_sum(float v) {
#pragma unroll
    for (int o = 16; o > 0; o >>= 1) v += __shfl_xor_sync(0xffffffffu, v, o);
    return v;
}

// ---------------- init affine to identity (for layer 0 consumers) --------------
__global__ void init_aff_kernel() {
    int t = threadIdx.x;
    if (t < 64) g_aff2[t] = 1.0f;
    else        g_aff2[t] = 0.0f;   // t in [64,128)
}

// ---------------- atom encoder: h[n] = sum_c atom_emb[c][x[n,c]] ----------------
__global__ void atom_kernel(const int* __restrict__ x, const float* __restrict__ aemb, int N) {
    int t = blockIdx.x * blockDim.x + threadIdx.x;
    int node = t >> 4, lane = t & 15;
    if (node >= N) return;
    float4 s = make_float4(0.f, 0.f, 0.f, 0.f);
#pragma unroll
    for (int c = 0; c < 9; c++) {
        int v = __ldg(&x[node * 9 + c]);
        float4 e = *(const float4*)&aemb[((size_t)(c * 64 + v)) * 64 + lane * 4];
        s.x += e.x; s.y += e.y; s.z += e.z; s.w += e.w;
    }
    *(float4*)&g_h[(size_t)node * 64 + lane * 4] = s;
}

// ================= CSR build (once per call; edge structure is layer-invariant) =
__global__ void hist_kernel(const int* __restrict__ ei, int E) {
    int e = blockIdx.x * blockDim.x + threadIdx.x;
    if (e < E) atomicAdd(&g_deg[__ldg(&ei[E + e])], 1);
}

// scanA: per-512 block exclusive scan of g_deg -> g_rowptr (local), totals -> g_part
__global__ __launch_bounds__(512) void scanA_kernel(int N) {
    __shared__ int s[512];
    int tx = threadIdx.x;
    int i = blockIdx.x * 512 + tx;
    int d = (i < N) ? g_deg[i] : 0;
    s[tx] = d;
    __syncthreads();
#pragma unroll
    for (int o = 1; o < 512; o <<= 1) {
        int v = (tx >= o) ? s[tx - o] : 0;
        __syncthreads();
        if (tx >= o) s[tx] += v;
        __syncthreads();
    }
    if (i < N) g_rowptr[i] = s[tx] - d;      // exclusive within block
    if (tx == 511) g_part[blockIdx.x] = s[511];
}

// scanB: one block, exclusive scan of block totals (nb <= 512)
__global__ __launch_bounds__(512) void scanB_kernel(int nb) {
    __shared__ int s[512];
    int tx = threadIdx.x;
    int d = (tx < nb) ? g_part[tx] : 0;
    s[tx] = d;
    __syncthreads();
#pragma unroll
    for (int o = 1; o < 512; o <<= 1) {
        int v = (tx >= o) ? s[tx - o] : 0;
        __syncthreads();
        if (tx >= o) s[tx] += v;
        __syncthreads();
    }
    if (tx < nb) g_part[tx] = s[tx] - d;
}

// scanC: add block offsets; init cursor; re-zero deg (keeps replay invariant)
__global__ __launch_bounds__(512) void scanC_kernel(int N, int E) {
    int i = blockIdx.x * 512 + threadIdx.x;
    if (i < N) {
        int v = g_rowptr[i] + g_part[blockIdx.x];
        g_rowptr[i] = v;
        g_cursor[i] = v;
        g_deg[i] = 0;
    }
    if (i == 0) g_rowptr[N] = E;
}

// scatter: bucket edges by dst; pack bond attrs (read ea ONCE per call)
__global__ void scatter_kernel(const int* __restrict__ ei, const int* __restrict__ ea, int E) {
    int e = blockIdx.x * blockDim.x + threadIdx.x;
    if (e >= E) return;
    int src = __ldg(&ei[e]);
    int dst = __ldg(&ei[E + e]);
    int pk = __ldg(&ea[e * 3 + 0]) | (__ldg(&ea[e * 3 + 1]) << 8) | (__ldg(&ea[e * 3 + 2]) << 16);
    int pos = atomicAdd(&g_cursor[dst], 1);
    g_edge[pos] = make_int2(src, pk);
}

// ---------------- agg kernel: agg[n] = sum_{e in CSR[n]} relu(heff[src]+ee) -----
// 16 lanes per dst node, 16 nodes per 256-thread block. No atomics, one write.
// 4-wide unrolled edge walk: 4 independent h-gathers in flight (MLP=4).
__global__ __launch_bounds__(256) void agg_kernel(const float* __restrict__ bt, int doRelu, int N) {
    __shared__ float sbt[3 * 8 * 64];
    __shared__ float sa[64], sc[64];
    int tid = threadIdx.x;
    for (int t = tid; t < 1536; t += 256) sbt[t] = bt[t];
    if (tid < 64) { sa[tid] = g_aff2[tid]; sc[tid] = g_aff2[64 + tid]; }
    __syncthreads();

    int lane = tid & 15, grp = tid >> 4;
    int n = blockIdx.x * 16 + grp;
    if (n >= N) return;
    int e0 = __ldg(&g_rowptr[n]);
    int e1 = __ldg(&g_rowptr[n + 1]);
    float4 a4 = *(float4*)&sa[lane * 4];
    float4 c4 = *(float4*)&sc[lane * 4];
    float4 acc = make_float4(0.f, 0.f, 0.f, 0.f);
    int lane4 = lane * 4;

#define AGG_PROC(ed, hv)                                                          \
    do {                                                                          \
        int pb0 = (ed).y & 255, pb1 = ((ed).y >> 8) & 255, pb2 = ((ed).y >> 16) & 255; \
        float4 v0 = *(float4*)&sbt[(0 * 8 + pb0) * 64 + lane4];                   \
        float4 v1 = *(float4*)&sbt[(1 * 8 + pb1) * 64 + lane4];                   \
        float4 v2 = *(float4*)&sbt[(2 * 8 + pb2) * 64 + lane4];                   \
        float h0 = fmaf(a4.x, (hv).x, c4.x);                                      \
        float h1 = fmaf(a4.y, (hv).y, c4.y);                                      \
        float h2 = fmaf(a4.z, (hv).z, c4.z);                                      \
        float h3 = fmaf(a4.w, (hv).w, c4.w);                                      \
        if (doRelu) { h0 = fmaxf(h0, 0.f); h1 = fmaxf(h1, 0.f);                   \
                      h2 = fmaxf(h2, 0.f); h3 = fmaxf(h3, 0.f); }                 \
        acc.x += fmaxf(h0 + v0.x + v1.x + v2.x, 0.f);                             \
        acc.y += fmaxf(h1 + v0.y + v1.y + v2.y, 0.f);                             \
        acc.z += fmaxf(h2 + v0.z + v1.z + v2.z, 0.f);                             \
        acc.w += fmaxf(h3 + v0.w + v1.w + v2.w, 0.f);                             \
    } while (0)

    int i = e0;
#pragma unroll 1
    for (; i + 4 <= e1; i += 4) {
        int2 ed0 = __ldg(&g_edge[i + 0]);
        int2 ed1 = __ldg(&g_edge[i + 1]);
        int2 ed2 = __ldg(&g_edge[i + 2]);
        int2 ed3 = __ldg(&g_edge[i + 3]);
        float4 hv0 = __ldg((const float4*)&g_h[(size_t)ed0.x * 64 + lane4]);
        float4 hv1 = __ldg((const float4*)&g_h[(size_t)ed1.x * 64 + lane4]);
        float4 hv2 = __ldg((const float4*)&g_h[(size_t)ed2.x * 64 + lane4]);
        float4 hv3 = __ldg((const float4*)&g_h[(size_t)ed3.x * 64 + lane4]);
        AGG_PROC(ed0, hv0);
        AGG_PROC(ed1, hv1);
        AGG_PROC(ed2, hv2);
        AGG_PROC(ed3, hv3);
    }
#pragma unroll 1
    for (; i < e1; i++) {
        int2 ed = __ldg(&g_edge[i]);
        float4 hv = __ldg((const float4*)&g_h[(size_t)ed.x * 64 + lane4]);
        AGG_PROC(ed, hv);
    }
#undef AGG_PROC

    *(float4*)&g_agg[(size_t)n * 64 + lane4] = acc;   // covers zero-degree too
}

// ---------------- GEMM1: Y = Z @ W1 + b1, Z = (1+eps)*heff + agg; stats(Y) -------
#define GEMM1_SMEM ((64 * 128 + 64 * 128 + 256) * sizeof(float))
__global__ __launch_bounds__(512, 2) void gemm1_kernel(int doRelu, const float* __restrict__ epsp,
                                                       const float* __restrict__ W1,
                                                       const float* __restrict__ bias1, int N) {
    extern __shared__ float sm[];
    float* Zs   = sm;                 // [k][m] 64x128
    float* Ws   = sm + 64 * 128;      // [k][n] 64x128
    float* ssum = Ws + 64 * 128;      // [128]
    float* ssq  = ssum + 128;         // [128]
    int tid = threadIdx.x;
    int rowBase = blockIdx.x * 128;
    float ope = 1.0f + *epsp;

    for (int t = tid; t < (64 * 128) / 4; t += 512)
        ((float4*)Ws)[t] = ((const float4*)W1)[t];

    for (int t = tid; t < 128 * 16; t += 512) {
        int r = t >> 4, kq = t & 15;
        int grow = rowBase + r;
        float4 hv, av;
        if (grow < N) {
            hv = ((const float4*)(g_h  + (size_t)grow * 64))[kq];
            av = ((const float4*)(g_agg + (size_t)grow * 64))[kq];
        } else {
            hv = make_float4(0.f, 0.f, 0.f, 0.f); av = hv;
        }
        float4 a4 = *(const float4*)(g_aff2 + kq * 4);
        float4 c4 = *(const float4*)(g_aff2 + 64 + kq * 4);
        float h0 = fmaf(a4.x, hv.x, c4.x), h1 = fmaf(a4.y, hv.y, c4.y);
        float h2 = fmaf(a4.z, hv.z, c4.z), h3 = fmaf(a4.w, hv.w, c4.w);
        if (doRelu) { h0 = fmaxf(h0, 0.f); h1 = fmaxf(h1, 0.f); h2 = fmaxf(h2, 0.f); h3 = fmaxf(h3, 0.f); }
        Zs[(kq * 4 + 0) * 128 + r] = fmaf(ope, h0, av.x);
        Zs[(kq * 4 + 1) * 128 + r] = fmaf(ope, h1, av.y);
        Zs[(kq * 4 + 2) * 128 + r] = fmaf(ope, h2, av.z);
        Zs[(kq * 4 + 3) * 128 + r] = fmaf(ope, h3, av.w);
    }
    if (tid < 128) { ssum[tid] = 0.f; ssq[tid] = 0.f; }
    __syncthreads();

    int tr = tid & 31;   // rows tr*4 .. tr*4+3
    int tc = tid >> 5;   // cols tc*8 .. tc*8+7 (whole warp shares tc)
    unsigned long long acc2[2][8];
#pragma unroll
    for (int i = 0; i < 2; i++)
#pragma unroll
        for (int j = 0; j < 8; j++) acc2[i][j] = 0ull;

#pragma unroll 4
    for (int k = 0; k < 64; ++k) {
        ulonglong2 ap = *(ulonglong2*)(Zs + k * 128 + tr * 4);   // 2 row-pairs
        float4 bv0 = *(float4*)(Ws + k * 128 + tc * 8);          // broadcast
        float4 bv1 = *(float4*)(Ws + k * 128 + tc * 8 + 4);      // broadcast
        {
            unsigned long long b0 = bcast2(bv0.x), b1 = bcast2(bv0.y),
                               b2 = bcast2(bv0.z), b3 = bcast2(bv0.w);
            ffma2(acc2[0][0], ap.x, b0); ffma2(acc2[1][0], ap.y, b0);
            ffma2(acc2[0][1], ap.x, b1); ffma2(acc2[1][1], ap.y, b1);
            ffma2(acc2[0][2], ap.x, b2); ffma2(acc2[1][2], ap.y, b2);
            ffma2(acc2[0][3], ap.x, b3); ffma2(acc2[1][3], ap.y, b3);
        }
        {
            unsigned long long b4 = bcast2(bv1.x), b5 = bcast2(bv1.y),
                               b6 = bcast2(bv1.z), b7 = bcast2(bv1.w);
            ffma2(acc2[0][4], ap.x, b4); ffma2(acc2[1][4], ap.y, b4);
            ffma2(acc2[0][5], ap.x, b5); ffma2(acc2[1][5], ap.y, b5);
            ffma2(acc2[0][6], ap.x, b6); ffma2(acc2[1][6], ap.y, b6);
            ffma2(acc2[0][7], ap.x, b7); ffma2(acc2[1][7], ap.y, b7);
        }
    }

    float4 bb0 = *(const float4*)(bias1 + tc * 8);
    float4 bb1 = *(const float4*)(bias1 + tc * 8 + 4);
    float bj[8] = {bb0.x, bb0.y, bb0.z, bb0.w, bb1.x, bb1.y, bb1.z, bb1.w};
    float csum[8] = {0, 0, 0, 0, 0, 0, 0, 0}, csq[8] = {0, 0, 0, 0, 0, 0, 0, 0};
#pragma unroll
    for (int ip = 0; ip < 2; ip++) {
#pragma unroll
        for (int half = 0; half < 2; half++) {
            int grow = rowBase + tr * 4 + ip * 2 + half;
            if (grow < N) {
                float y[8];
#pragma unroll
                for (int j = 0; j < 8; j++) {
                    float2 p = unpack2(acc2[ip][j]);
                    float v = (half == 0 ? p.x : p.y) + bj[j];
                    y[j] = v;
                    csum[j] += v;
                    csq[j]  += v * v;
                }
                float* yp = g_y + (size_t)grow * 128 + tc * 8;
                *(float4*)yp       = make_float4(y[0], y[1], y[2], y[3]);
                *(float4*)(yp + 4) = make_float4(y[4], y[5], y[6], y[7]);
            }
        }
    }
#pragma unroll
    for (int j = 0; j < 8; j++) {
        float s = warp_sum(csum[j]);
        float q = warp_sum(csq[j]);
        if ((tid & 31) == 0) {
            atomicAdd(&ssum[tc * 8 + j], s);
            atomicAdd(&ssq [tc * 8 + j], q);
        }
    }
    __syncthreads();
    if (tid < 128) {
        atomicAdd(&g_stats[tid],       ssum[tid]);
        atomicAdd(&g_stats[128 + tid], ssq[tid]);
    }
}

// ---------------- reduce1: stats -> BN1 affine (a1,c1); zero consumed stats -----
__global__ void reduce1_kernel(const float* __restrict__ gam, const float* __restrict__ bet, float invN) {
    int c = threadIdx.x;   // 128
    float s = g_stats[c], sq = g_stats[128 + c];
    float m = s * invN;
    float v = sq * invN - m * m;
    float r = rsqrtf(v + 1e-5f);
    float a = gam[c] * r;
    g_aff1[c]       = a;
    g_aff1[128 + c] = bet[c] - m * a;
    g_stats[c] = 0.f;
    g_stats[128 + c] = 0.f;
}

// ---------------- GEMM2: T = relu(aff1(Y)) @ W2 + b2; stats(T); T -> g_h --------
#define GEMM2_SMEM ((64 * 128 + 64 * 64 + 128) * sizeof(float))
__global__ __launch_bounds__(512, 2) void gemm2_kernel(const float* __restrict__ W2,
                                                       const float* __restrict__ bias2, int N) {
    extern __shared__ float sm[];
    float* Ys   = sm;               // [k][m] 64x128 (per chunk)
    float* Ws2  = sm + 64 * 128;    // [k][n] 64x64
    float* ssum = Ws2 + 64 * 64;    // [64]
    float* ssq  = ssum + 64;        // [64]
    int tid = threadIdx.x;
    int rowBase = blockIdx.x * 128;
    int tr = tid & 31;   // rows tr*4 .. +3
    int tc = tid >> 5;   // cols tc*4 .. +3

    if (tid < 64) { ssum[tid] = 0.f; ssq[tid] = 0.f; }

    unsigned long long acc2[2][4];
#pragma unroll
    for (int i = 0; i < 2; i++)
#pragma unroll
        for (int j = 0; j < 4; j++) acc2[i][j] = 0ull;

#pragma unroll 1
    for (int kc = 0; kc < 2; ++kc) {
        if (kc) __syncthreads();   // protect smem reuse across chunks
        for (int t = tid; t < (64 * 64) / 4; t += 512)
            ((float4*)Ws2)[t] = ((const float4*)(W2 + kc * 64 * 64))[t];
        for (int t = tid; t < 128 * 16; t += 512) {
            int r = t >> 4, kq = t & 15;
            int grow = rowBase + r;
            float4 yv = (grow < N) ? ((const float4*)(g_y + (size_t)grow * 128))[kc * 16 + kq]
                                   : make_float4(0.f, 0.f, 0.f, 0.f);
            int kb = kc * 64 + kq * 4;
            float4 a4 = *(const float4*)(g_aff1 + kb);
            float4 c4 = *(const float4*)(g_aff1 + 128 + kb);
            Ys[(kq * 4 + 0) * 128 + r] = fmaxf(fmaf(a4.x, yv.x, c4.x), 0.f);
            Ys[(kq * 4 + 1) * 128 + r] = fmaxf(fmaf(a4.y, yv.y, c4.y), 0.f);
            Ys[(kq * 4 + 2) * 128 + r] = fmaxf(fmaf(a4.z, yv.z, c4.z), 0.f);
            Ys[(kq * 4 + 3) * 128 + r] = fmaxf(fmaf(a4.w, yv.w, c4.w), 0.f);
        }
        __syncthreads();
#pragma unroll 4
        for (int k = 0; k < 64; ++k) {
            ulonglong2 ap = *(ulonglong2*)(Ys + k * 128 + tr * 4);
            float4 bv = *(float4*)(Ws2 + k * 64 + tc * 4);   // broadcast
            unsigned long long b0 = bcast2(bv.x), b1 = bcast2(bv.y),
                               b2 = bcast2(bv.z), b3 = bcast2(bv.w);
            ffma2(acc2[0][0], ap.x, b0); ffma2(acc2[1][0], ap.y, b0);
            ffma2(acc2[0][1], ap.x, b1); ffma2(acc2[1][1], ap.y, b1);
            ffma2(acc2[0][2], ap.x, b2); ffma2(acc2[1][2], ap.y, b2);
            ffma2(acc2[0][3], ap.x, b3); ffma2(acc2[1][3], ap.y, b3);
        }
    }

    float4 bbv = *(const float4*)(bias2 + tc * 4);
    float bj[4] = {bbv.x, bbv.y, bbv.z, bbv.w};
    float csum[4] = {0, 0, 0, 0}, csq[4] = {0, 0, 0, 0};
#pragma unroll
    for (int ip = 0; ip < 2; ip++) {
#pragma unroll
        for (int half = 0; half < 2; half++) {
            int grow = rowBase + tr * 4 + ip * 2 + half;
            if (grow < N) {
                float tv[4];
#pragma unroll
                for (int j = 0; j < 4; j++) {
                    float2 p = unpack2(acc2[ip][j]);
                    float v = (half == 0 ? p.x : p.y) + bj[j];
                    tv[j] = v;
                    csum[j] += v;
                    csq[j]  += v * v;
                }
                *(float4*)(g_h + (size_t)grow * 64 + tc * 4) = make_float4(tv[0], tv[1], tv[2], tv[3]);
            }
        }
    }
#pragma unroll
    for (int j = 0; j < 4; j++) {
        float s = warp_sum(csum[j]);
        float q = warp_sum(csq[j]);
        if ((tid & 31) == 0) {
            atomicAdd(&ssum[tc * 4 + j], s);
            atomicAdd(&ssq [tc * 4 + j], q);
        }
    }
    __syncthreads();
    if (tid < 64) {
        atomicAdd(&g_stats[256 + tid], ssum[tid]);
        atomicAdd(&g_stats[320 + tid], ssq[tid]);
    }
}

// ---------------- reduce2: stats -> outer BN affine (a2,c2); zero stats ---------
__global__ void reduce2_kernel(const float* __restrict__ gam, const float* __restrict__ bet, float invN) {
    int c = threadIdx.x;   // 64
    float s = g_stats[256 + c], sq = g_stats[320 + c];
    float m = s * invN;
    float v = sq * invN - m * m;
    float r = rsqrtf(v + 1e-5f);
    float a = gam[c] * r;
    g_aff2[c]      = a;
    g_aff2[64 + c] = bet[c] - m * a;
    g_stats[256 + c] = 0.f;
    g_stats[320 + c] = 0.f;
}

// ---------------- final: out = aff2(g_h) (no relu) ; append batch ---------------
__global__ void final_kernel(const int* __restrict__ batch, float* __restrict__ out,
                             int N, long long outn) {
    int t = blockIdx.x * blockDim.x + threadIdx.x;
    int node = t >> 4, lane = t & 15;
    if (node < N) {
        float4 a4 = *(const float4*)(g_aff2 + lane * 4);
        float4 c4 = *(const float4*)(g_aff2 + 64 + lane * 4);
        float4 tv = *(const float4*)(g_h + (size_t)node * 64 + lane * 4);
        float4 o;
        o.x = fmaf(a4.x, tv.x, c4.x);
        o.y = fmaf(a4.y, tv.y, c4.y);
        o.z = fmaf(a4.z, tv.z, c4.z);
        o.w = fmaf(a4.w, tv.w, c4.w);
        *(float4*)(out + (size_t)node * 64 + lane * 4) = o;
    }
    if (t < N && outn >= (long long)N * 64 + N)
        out[(size_t)N * 64 + t] = (float)batch[t];
}

// -------------------------------- host side ------------------------------------
extern "C" void kernel_launch(void* const* d_in, const int* in_sizes, int n_in,
                              void* d_out, int out_size) {
    const int*   x        = (const int*)d_in[0];
    const int*   ei       = (const int*)d_in[1];
    const int*   ea       = (const int*)d_in[2];
    const int*   batch    = (const int*)d_in[3];
    const float* atom_emb = (const float*)d_in[4];
    const float* bond_emb = (const float*)d_in[5];
    const float* eps      = (const float*)d_in[6];
    const float* W1       = (const float*)d_in[7];
    const float* b1       = (const float*)d_in[8];
    const float* bn1_g    = (const float*)d_in[9];
    const float* bn1_b    = (const float*)d_in[10];
    const float* W2       = (const float*)d_in[11];
    const float* b2       = (const float*)d_in[12];
    const float* bn_g     = (const float*)d_in[13];
    const float* bn_b     = (const float*)d_in[14];

    int N = in_sizes[0] / 9;
    int E = in_sizes[1] / 2;
    float invN = 1.0f / (float)N;

    // one-time host-side setup (smem opt-in)
    static bool inited = false;
    if (!inited) {
        cudaFuncSetAttribute(gemm1_kernel, cudaFuncAttributeMaxDynamicSharedMemorySize, (int)GEMM1_SMEM);
        cudaFuncSetAttribute(gemm2_kernel, cudaFuncAttributeMaxDynamicSharedMemorySize, (int)GEMM2_SMEM);
        inited = true;
    }

    int nodeBlocks = (N * 16 + 255) / 256;
    int rowBlocks  = (N + 127) / 128;
    int eBlocks    = (E + 255) / 256;
    int scanBlocks = (N + 511) / 512;      // <= 512 for MAXN=100000
    int aggBlocks  = (N + 15) / 16;

    // node features + CSR build (edge structure is shared by all 4 layers)
    atom_kernel<<<nodeBlocks, 256>>>(x, atom_emb, N);
    init_aff_kernel<<<1, 128>>>();
    hist_kernel<<<eBlocks, 256>>>(ei, E);
    scanA_kernel<<<scanBlocks, 512>>>(N);
    scanB_kernel<<<1, 512>>>(scanBlocks);
    scanC_kernel<<<scanBlocks, 512>>>(N, E);
    scatter_kernel<<<eBlocks, 256>>>(ei, ea, E);

    for (int l = 0; l < NLAYER; ++l) {
        agg_kernel<<<aggBlocks, 256>>>(bond_emb + (size_t)l * 3 * 8 * 64, (l > 0) ? 1 : 0, N);
        gemm1_kernel<<<rowBlocks, 512, GEMM1_SMEM>>>((l > 0) ? 1 : 0, eps + l,
                                                     W1 + (size_t)l * 64 * 128,
                                                     b1 + (size_t)l * 128, N);
        reduce1_kernel<<<1, 128>>>(bn1_g + (size_t)l * 128, bn1_b + (size_t)l * 128, invN);
        gemm2_kernel<<<rowBlocks, 512, GEMM2_SMEM>>>(W2 + (size_t)l * 128 * 64,
                                                     b2 + (size_t)l * 64, N);
        reduce2_kernel<<<1, 64>>>(bn_g + (size_t)l * 64, bn_b + (size_t)l * 64, invN);
    }

    final_kernel<<<nodeBlocks, 256>>>(batch, (float*)d_out, N, (long long)out_size);
}

// round 13
// speedup vs baseline: 1.1141x; 1.1141x over previous
#include <cuda_runtime.h>
#include <cuda_bf16.h>

#define EMB 64
#define MAXN 100000
#define MAXE 1000000
#define NLAYER 4
#define ZS_STRIDE 132   // padded smem stride for A-tiles (16B aligned, breaks STS conflicts)

// ---------------- scratch (__device__ globals: allocation-free) ----------------
__device__ float g_h[(size_t)MAXN * 64];          // current node features (raw, pre-affine)
__device__ float g_agg[(size_t)MAXN * 64];        // aggregation result
__device__ float g_y[(size_t)MAXN * 128];         // GEMM1 output
__device__ float g_stats[384];                    // [sum128, sq128, sum64, sq64] (BSS zero)
__device__ float g_aff1[256];                     // BN1 affine: a[128], c[128]
__device__ float g_aff2[128];                     // outer BN affine: a[64], c[64]
// CSR build scratch (all re-established every call; g_deg zeroed by scanC)
__device__ int  g_deg[MAXN];
__device__ int  g_rowptr[MAXN + 1];
__device__ int  g_part[512];
__device__ int  g_cursor[MAXN];
__device__ int2 g_edge[MAXE];                     // {src, b0|b1<<8|b2<<16}

// ---------------- f32x2 packed-FMA helpers (sm_103a) ----------------------------
__device__ __forceinline__ void ffma2(unsigned long long& d, unsigned long long a,
                                      unsigned long long b) {
    asm("fma.rn.f32x2 %0, %1, %2, %0;" : "+l"(d) : "l"(a), "l"(b));
}
__device__ __forceinline__ unsigned long long bcast2(float v) {
    unsigned long long r;
    asm("mov.b64 %0, {%1, %1};" : "=l"(r) : "f"(v));
    return r;
}
__device__ __forceinline__ float2 unpack2(unsigned long long v) {
    float2 r;
    asm("mov.b64 {%0, %1}, %2;" : "=f"(r.x), "=f"(r.y) : "l"(v));
    return r;
}

// ---------------- init affine to identity (for layer 0 consumers) --------------
__global__ void init_aff_kernel() {
    int t = threadIdx.x;
    if (t < 64) g_aff2[t] = 1.0f;
    else        g_aff2[t] = 0.0f;   // t in [64,128)
}

// ---------------- atom encoder: h[n] = sum_c atom_emb[c][x[n,c]] ----------------
__global__ void atom_kernel(const int* __restrict__ x, const float* __restrict__ aemb, int N) {
    int t = blockIdx.x * blockDim.x + threadIdx.x;
    int node = t >> 4, lane = t & 15;
    if (node >= N) return;
    float4 s = make_float4(0.f, 0.f, 0.f, 0.f);
#pragma unroll
    for (int c = 0; c < 9; c++) {
        int v = __ldg(&x[node * 9 + c]);
        float4 e = *(const float4*)&aemb[((size_t)(c * 64 + v)) * 64 + lane * 4];
        s.x += e.x; s.y += e.y; s.z += e.z; s.w += e.w;
    }
    *(float4*)&g_h[(size_t)node * 64 + lane * 4] = s;
}

// ================= CSR build (once per call; edge structure is layer-invariant) =
__global__ void hist_kernel(const int* __restrict__ ei, int E) {
    int e = blockIdx.x * blockDim.x + threadIdx.x;
    if (e < E) atomicAdd(&g_deg[__ldg(&ei[E + e])], 1);
}

__global__ __launch_bounds__(512) void scanA_kernel(int N) {
    __shared__ int s[512];
    int tx = threadIdx.x;
    int i = blockIdx.x * 512 + tx;
    int d = (i < N) ? g_deg[i] : 0;
    s[tx] = d;
    __syncthreads();
#pragma unroll
    for (int o = 1; o < 512; o <<= 1) {
        int v = (tx >= o) ? s[tx - o] : 0;
        __syncthreads();
        if (tx >= o) s[tx] += v;
        __syncthreads();
    }
    if (i < N) g_rowptr[i] = s[tx] - d;      // exclusive within block
    if (tx == 511) g_part[blockIdx.x] = s[511];
}

__global__ __launch_bounds__(512) void scanB_kernel(int nb) {
    __shared__ int s[512];
    int tx = threadIdx.x;
    int d = (tx < nb) ? g_part[tx] : 0;
    s[tx] = d;
    __syncthreads();
#pragma unroll
    for (int o = 1; o < 512; o <<= 1) {
        int v = (tx >= o) ? s[tx - o] : 0;
        __syncthreads();
        if (tx >= o) s[tx] += v;
        __syncthreads();
    }
    if (tx < nb) g_part[tx] = s[tx] - d;
}

__global__ __launch_bounds__(512) void scanC_kernel(int N, int E) {
    int i = blockIdx.x * 512 + threadIdx.x;
    if (i < N) {
        int v = g_rowptr[i] + g_part[blockIdx.x];
        g_rowptr[i] = v;
        g_cursor[i] = v;
        g_deg[i] = 0;
    }
    if (i == 0) g_rowptr[N] = E;
}

__global__ void scatter_kernel(const int* __restrict__ ei, const int* __restrict__ ea, int E) {
    int e = blockIdx.x * blockDim.x + threadIdx.x;
    if (e >= E) return;
    int src = __ldg(&ei[e]);
    int dst = __ldg(&ei[E + e]);
    int pk = __ldg(&ea[e * 3 + 0]) | (__ldg(&ea[e * 3 + 1]) << 8) | (__ldg(&ea[e * 3 + 2]) << 16);
    int pos = atomicAdd(&g_cursor[dst], 1);
    g_edge[pos] = make_int2(src, pk);
}

// ---------------- agg kernel: agg[n] = sum_{e in CSR[n]} relu(heff[src]+ee) -----
__global__ __launch_bounds__(256) void agg_kernel(const float* __restrict__ bt, int doRelu, int N) {
    __shared__ float sbt[3 * 8 * 64];
    __shared__ float sa[64], sc[64];
    int tid = threadIdx.x;
    for (int t = tid; t < 1536; t += 256) sbt[t] = bt[t];
    if (tid < 64) { sa[tid] = g_aff2[tid]; sc[tid] = g_aff2[64 + tid]; }
    __syncthreads();

    int lane = tid & 15, grp = tid >> 4;
    int n = blockIdx.x * 16 + grp;
    if (n >= N) return;
    int e0 = __ldg(&g_rowptr[n]);
    int e1 = __ldg(&g_rowptr[n + 1]);
    float4 a4 = *(float4*)&sa[lane * 4];
    float4 c4 = *(float4*)&sc[lane * 4];
    float4 acc = make_float4(0.f, 0.f, 0.f, 0.f);

    int2 ed;
    if (e0 < e1) ed = __ldg(&g_edge[e0]);
#pragma unroll 1
    for (int i = e0; i < e1; i++) {
        int2 nxt;
        if (i + 1 < e1) nxt = __ldg(&g_edge[i + 1]);   // prefetch
        int src = ed.x;
        int b0 = ed.y & 255, b1 = (ed.y >> 8) & 255, b2 = (ed.y >> 16) & 255;
        float4 hv = __ldg((const float4*)&g_h[(size_t)src * 64 + lane * 4]);
        float4 e0v = *(float4*)&sbt[(0 * 8 + b0) * 64 + lane * 4];
        float4 e1v = *(float4*)&sbt[(1 * 8 + b1) * 64 + lane * 4];
        float4 e2v = *(float4*)&sbt[(2 * 8 + b2) * 64 + lane * 4];
        float h0 = fmaf(a4.x, hv.x, c4.x);
        float h1 = fmaf(a4.y, hv.y, c4.y);
        float h2 = fmaf(a4.z, hv.z, c4.z);
        float h3 = fmaf(a4.w, hv.w, c4.w);
        if (doRelu) { h0 = fmaxf(h0, 0.f); h1 = fmaxf(h1, 0.f); h2 = fmaxf(h2, 0.f); h3 = fmaxf(h3, 0.f); }
        acc.x += fmaxf(h0 + e0v.x + e1v.x + e2v.x, 0.f);
        acc.y += fmaxf(h1 + e0v.y + e1v.y + e2v.y, 0.f);
        acc.z += fmaxf(h2 + e0v.z + e1v.z + e2v.z, 0.f);
        acc.w += fmaxf(h3 + e0v.w + e1v.w + e2v.w, 0.f);
        ed = nxt;
    }
    *(float4*)&g_agg[(size_t)n * 64 + lane * 4] = acc;   // covers zero-degree too
}

// ---------------- GEMM1: Y = Z @ W1 + b1, Z = (1+eps)*heff + agg; stats(Y) -------
// block tile 128x128, K=64, 512 threads.
// 2-D warp grid: 4 row-warps x 4 col-warps, warp tile 32x32.
// lane grid: rl = lane&7 (4 rows each), cl = lane>>3 (8 cols each).
// A load: 8 unique 16B addrs = 128B = 1 phase; each B float4: 4 unique = 1 phase.
#define GEMM1_SMEM ((64 * ZS_STRIDE + 64 * 128 + 256) * sizeof(float))
__global__ __launch_bounds__(512, 2) void gemm1_kernel(int doRelu, const float* __restrict__ epsp,
                                                       const float* __restrict__ W1,
                                                       const float* __restrict__ bias1, int N) {
    extern __shared__ float sm[];
    float* Zs   = sm;                       // [k][m] 64 x ZS_STRIDE (128 used)
    float* Ws   = sm + 64 * ZS_STRIDE;      // [k][n] 64x128
    float* ssum = Ws + 64 * 128;            // [128]
    float* ssq  = ssum + 128;               // [128]
    int tid = threadIdx.x;
    int rowBase = blockIdx.x * 128;
    float ope = 1.0f + *epsp;

    for (int t = tid; t < (64 * 128) / 4; t += 512)
        ((float4*)Ws)[t] = ((const float4*)W1)[t];

    // staging: warp = 4 rows x 8 kq8 -> coalesced gathers, 4-way STS conflicts max
    for (int t = tid; t < 128 * 8; t += 512) {
        int r = t >> 3, kq8 = t & 7;
        int grow = rowBase + r;
#pragma unroll
        for (int hh = 0; hh < 2; hh++) {
            int kq = kq8 + hh * 8;
            float4 hv, av;
            if (grow < N) {
                hv = ((const float4*)(g_h  + (size_t)grow * 64))[kq];
                av = ((const float4*)(g_agg + (size_t)grow * 64))[kq];
            } else {
                hv = make_float4(0.f, 0.f, 0.f, 0.f); av = hv;
            }
            float4 a4 = *(const float4*)(g_aff2 + kq * 4);
            float4 c4 = *(const float4*)(g_aff2 + 64 + kq * 4);
            float h0 = fmaf(a4.x, hv.x, c4.x), h1 = fmaf(a4.y, hv.y, c4.y);
            float h2 = fmaf(a4.z, hv.z, c4.z), h3 = fmaf(a4.w, hv.w, c4.w);
            if (doRelu) { h0 = fmaxf(h0, 0.f); h1 = fmaxf(h1, 0.f); h2 = fmaxf(h2, 0.f); h3 = fmaxf(h3, 0.f); }
            Zs[(kq * 4 + 0) * ZS_STRIDE + r] = fmaf(ope, h0, av.x);
            Zs[(kq * 4 + 1) * ZS_STRIDE + r] = fmaf(ope, h1, av.y);
            Zs[(kq * 4 + 2) * ZS_STRIDE + r] = fmaf(ope, h2, av.z);
            Zs[(kq * 4 + 3) * ZS_STRIDE + r] = fmaf(ope, h3, av.w);
        }
    }
    if (tid < 128) { ssum[tid] = 0.f; ssq[tid] = 0.f; }
    __syncthreads();

    int lane = tid & 31, wid = tid >> 5;
    int warpR = wid & 3, warpC = wid >> 2;
    int rl = lane & 7, cl = lane >> 3;
    int rowOff = warpR * 32 + rl * 4;   // 4 rows (2 f32x2 pairs)
    int colOff = warpC * 32 + cl * 8;   // 8 cols

    unsigned long long acc2[2][8];
#pragma unroll
    for (int i = 0; i < 2; i++)
#pragma unroll
        for (int j = 0; j < 8; j++) acc2[i][j] = 0ull;

#pragma unroll 4
    for (int k = 0; k < 64; ++k) {
        ulonglong2 ap = *(ulonglong2*)(Zs + k * ZS_STRIDE + rowOff);
        float4 bv0 = *(float4*)(Ws + k * 128 + colOff);
        float4 bv1 = *(float4*)(Ws + k * 128 + colOff + 4);
        {
            unsigned long long b0 = bcast2(bv0.x), b1 = bcast2(bv0.y),
                               b2 = bcast2(bv0.z), b3 = bcast2(bv0.w);
            ffma2(acc2[0][0], ap.x, b0); ffma2(acc2[1][0], ap.y, b0);
            ffma2(acc2[0][1], ap.x, b1); ffma2(acc2[1][1], ap.y, b1);
            ffma2(acc2[0][2], ap.x, b2); ffma2(acc2[1][2], ap.y, b2);
            ffma2(acc2[0][3], ap.x, b3); ffma2(acc2[1][3], ap.y, b3);
        }
        {
            unsigned long long b4 = bcast2(bv1.x), b5 = bcast2(bv1.y),
                               b6 = bcast2(bv1.z), b7 = bcast2(bv1.w);
            ffma2(acc2[0][4], ap.x, b4); ffma2(acc2[1][4], ap.y, b4);
            ffma2(acc2[0][5], ap.x, b5); ffma2(acc2[1][5], ap.y, b5);
            ffma2(acc2[0][6], ap.x, b6); ffma2(acc2[1][6], ap.y, b6);
            ffma2(acc2[0][7], ap.x, b7); ffma2(acc2[1][7], ap.y, b7);
        }
    }

    float4 bb0 = *(const float4*)(bias1 + colOff);
    float4 bb1 = *(const float4*)(bias1 + colOff + 4);
    float bj[8] = {bb0.x, bb0.y, bb0.z, bb0.w, bb1.x, bb1.y, bb1.z, bb1.w};
    float csum[8] = {0, 0, 0, 0, 0, 0, 0, 0}, csq[8] = {0, 0, 0, 0, 0, 0, 0, 0};
#pragma unroll
    for (int ip = 0; ip < 2; ip++) {
#pragma unroll
        for (int half = 0; half < 2; half++) {
            int grow = rowBase + rowOff + ip * 2 + half;
            if (grow < N) {
                float y[8];
#pragma unroll
                for (int j = 0; j < 8; j++) {
                    float2 p = unpack2(acc2[ip][j]);
                    float v = (half == 0 ? p.x : p.y) + bj[j];
                    y[j] = v;
                    csum[j] += v;
                    csq[j]  += v * v;
                }
                float* yp = g_y + (size_t)grow * 128 + colOff;
                *(float4*)yp       = make_float4(y[0], y[1], y[2], y[3]);
                *(float4*)(yp + 4) = make_float4(y[4], y[5], y[6], y[7]);
            }
        }
    }
    // segmented reduce over rl (8-lane groups share the same cols), then 1 atomic/col
#pragma unroll
    for (int j = 0; j < 8; j++) {
        float s = csum[j], q = csq[j];
        s += __shfl_xor_sync(0xffffffffu, s, 1);
        s += __shfl_xor_sync(0xffffffffu, s, 2);
        s += __shfl_xor_sync(0xffffffffu, s, 4);
        q += __shfl_xor_sync(0xffffffffu, q, 1);
        q += __shfl_xor_sync(0xffffffffu, q, 2);
        q += __shfl_xor_sync(0xffffffffu, q, 4);
        if (rl == 0) {
            atomicAdd(&ssum[colOff + j], s);
            atomicAdd(&ssq [colOff + j], q);
        }
    }
    __syncthreads();
    if (tid < 128) {
        atomicAdd(&g_stats[tid],       ssum[tid]);
        atomicAdd(&g_stats[128 + tid], ssq[tid]);
    }
}

// ---------------- reduce1: stats -> BN1 affine (a1,c1); zero consumed stats -----
__global__ void reduce1_kernel(const float* __restrict__ gam, const float* __restrict__ bet, float invN) {
    int c = threadIdx.x;   // 128
    float s = g_stats[c], sq = g_stats[128 + c];
    float m = s * invN;
    float v = sq * invN - m * m;
    float r = rsqrtf(v + 1e-5f);
    float a = gam[c] * r;
    g_aff1[c]       = a;
    g_aff1[128 + c] = bet[c] - m * a;
    g_stats[c] = 0.f;
    g_stats[128 + c] = 0.f;
}

// ---------------- GEMM2: T = relu(aff1(Y)) @ W2 + b2; stats(T); T -> g_h --------
// block tile 128x64, K=128 in 2 chunks of 64. 512 threads.
// 2-D warp grid: 8 row-warps x 2 col-warps, warp tile 16x32.
// lane grid: rl = lane&3 (4 rows), cl = lane>>2 (4 cols).
#define GEMM2_SMEM ((64 * ZS_STRIDE + 64 * 64 + 128) * sizeof(float))
__global__ __launch_bounds__(512, 2) void gemm2_kernel(const float* __restrict__ W2,
                                                       const float* __restrict__ bias2, int N) {
    extern __shared__ float sm[];
    float* Ys   = sm;                      // [k][m] 64 x ZS_STRIDE (per chunk)
    float* Ws2  = sm + 64 * ZS_STRIDE;     // [k][n] 64x64
    float* ssum = Ws2 + 64 * 64;           // [64]
    float* ssq  = ssum + 64;               // [64]
    int tid = threadIdx.x;
    int rowBase = blockIdx.x * 128;

    int lane = tid & 31, wid = tid >> 5;
    int warpR = wid & 7, warpC = wid >> 3;
    int rl = lane & 3, cl = lane >> 2;
    int rowOff = warpR * 16 + rl * 4;   // 4 rows
    int colOff = warpC * 32 + cl * 4;   // 4 cols

    if (tid < 64) { ssum[tid] = 0.f; ssq[tid] = 0.f; }

    unsigned long long acc2[2][4];
#pragma unroll
    for (int i = 0; i < 2; i++)
#pragma unroll
        for (int j = 0; j < 4; j++) acc2[i][j] = 0ull;

#pragma unroll 1
    for (int kc = 0; kc < 2; ++kc) {
        if (kc) __syncthreads();   // protect smem reuse across chunks
        for (int t = tid; t < (64 * 64) / 4; t += 512)
            ((float4*)Ws2)[t] = ((const float4*)(W2 + kc * 64 * 64))[t];
        for (int t = tid; t < 128 * 8; t += 512) {
            int r = t >> 3, kq8 = t & 7;
            int grow = rowBase + r;
#pragma unroll
            for (int hh = 0; hh < 2; hh++) {
                int kq = kq8 + hh * 8;
                float4 yv = (grow < N) ? ((const float4*)(g_y + (size_t)grow * 128))[kc * 16 + kq]
                                       : make_float4(0.f, 0.f, 0.f, 0.f);
                int kb = kc * 64 + kq * 4;
                float4 a4 = *(const float4*)(g_aff1 + kb);
                float4 c4 = *(const float4*)(g_aff1 + 128 + kb);
                Ys[(kq * 4 + 0) * ZS_STRIDE + r] = fmaxf(fmaf(a4.x, yv.x, c4.x), 0.f);
                Ys[(kq * 4 + 1) * ZS_STRIDE + r] = fmaxf(fmaf(a4.y, yv.y, c4.y), 0.f);
                Ys[(kq * 4 + 2) * ZS_STRIDE + r] = fmaxf(fmaf(a4.z, yv.z, c4.z), 0.f);
                Ys[(kq * 4 + 3) * ZS_STRIDE + r] = fmaxf(fmaf(a4.w, yv.w, c4.w), 0.f);
            }
        }
        __syncthreads();
#pragma unroll 4
        for (int k = 0; k < 64; ++k) {
            ulonglong2 ap = *(ulonglong2*)(Ys + k * ZS_STRIDE + rowOff);
            float4 bv = *(float4*)(Ws2 + k * 64 + colOff);
            unsigned long long b0 = bcast2(bv.x), b1 = bcast2(bv.y),
                               b2 = bcast2(bv.z), b3 = bcast2(bv.w);
            ffma2(acc2[0][0], ap.x, b0); ffma2(acc2[1][0], ap.y, b0);
            ffma2(acc2[0][1], ap.x, b1); ffma2(acc2[1][1], ap.y, b1);
            ffma2(acc2[0][2], ap.x, b2); ffma2(acc2[1][2], ap.y, b2);
            ffma2(acc2[0][3], ap.x, b3); ffma2(acc2[1][3], ap.y, b3);
        }
    }

    float4 bbv = *(const float4*)(bias2 + colOff);
    float bj[4] = {bbv.x, bbv.y, bbv.z, bbv.w};
    float csum[4] = {0, 0, 0, 0}, csq[4] = {0, 0, 0, 0};
#pragma unroll
    for (int ip = 0; ip < 2; ip++) {
#pragma unroll
        for (int half = 0; half < 2; half++) {
            int grow = rowBase + rowOff + ip * 2 + half;
            if (grow < N) {
                float tv[4];
#pragma unroll
                for (int j = 0; j < 4; j++) {
                    float2 p = unpack2(acc2[ip][j]);
                    float v = (half == 0 ? p.x : p.y) + bj[j];
                    tv[j] = v;
                    csum[j] += v;
                    csq[j]  += v * v;
                }
                *(float4*)(g_h + (size_t)grow * 64 + colOff) = make_float4(tv[0], tv[1], tv[2], tv[3]);
            }
        }
    }
    // segmented reduce over rl (4-lane groups share cols), then 1 atomic/col
#pragma unroll
    for (int j = 0; j < 4; j++) {
        float s = csum[j], q = csq[j];
        s += __shfl_xor_sync(0xffffffffu, s, 1);
        s += __shfl_xor_sync(0xffffffffu, s, 2);
        q += __shfl_xor_sync(0xffffffffu, q, 1);
        q += __shfl_xor_sync(0xffffffffu, q, 2);
        if (rl == 0) {
            atomicAdd(&ssum[colOff + j], s);
            atomicAdd(&ssq [colOff + j], q);
        }
    }
    __syncthreads();
    if (tid < 64) {
        atomicAdd(&g_stats[256 + tid], ssum[tid]);
        atomicAdd(&g_stats[320 + tid], ssq[tid]);
    }
}

// ---------------- reduce2: stats -> outer BN affine (a2,c2); zero stats ---------
__global__ void reduce2_kernel(const float* __restrict__ gam, const float* __restrict__ bet, float invN) {
    int c = threadIdx.x;   // 64
    float s = g_stats[256 + c], sq = g_stats[320 + c];
    float m = s * invN;
    float v = sq * invN - m * m;
    float r = rsqrtf(v + 1e-5f);
    float a = gam[c] * r;
    g_aff2[c]      = a;
    g_aff2[64 + c] = bet[c] - m * a;
    g_stats[256 + c] = 0.f;
    g_stats[320 + c] = 0.f;
}

// ---------------- final: out = aff2(g_h) (no relu) ; append batch ---------------
__global__ void final_kernel(const int* __restrict__ batch, float* __restrict__ out,
                             int N, long long outn) {
    int t = blockIdx.x * blockDim.x + threadIdx.x;
    int node = t >> 4, lane = t & 15;
    if (node < N) {
        float4 a4 = *(const float4*)(g_aff2 + lane * 4);
        float4 c4 = *(const float4*)(g_aff2 + 64 + lane * 4);
        float4 tv = *(const float4*)(g_h + (size_t)node * 64 + lane * 4);
        float4 o;
        o.x = fmaf(a4.x, tv.x, c4.x);
        o.y = fmaf(a4.y, tv.y, c4.y);
        o.z = fmaf(a4.z, tv.z, c4.z);
        o.w = fmaf(a4.w, tv.w, c4.w);
        *(float4*)(out + (size_t)node * 64 + lane * 4) = o;
    }
    if (t < N && outn >= (long long)N * 64 + N)
        out[(size_t)N * 64 + t] = (float)batch[t];
}

// -------------------------------- host side ------------------------------------
extern "C" void kernel_launch(void* const* d_in, const int* in_sizes, int n_in,
                              void* d_out, int out_size) {
    const int*   x        = (const int*)d_in[0];
    const int*   ei       = (const int*)d_in[1];
    const int*   ea       = (const int*)d_in[2];
    const int*   batch    = (const int*)d_in[3];
    const float* atom_emb = (const float*)d_in[4];
    const float* bond_emb = (const float*)d_in[5];
    const float* eps      = (const float*)d_in[6];
    const float* W1       = (const float*)d_in[7];
    const float* b1       = (const float*)d_in[8];
    const float* bn1_g    = (const float*)d_in[9];
    const float* bn1_b    = (const float*)d_in[10];
    const float* W2       = (const float*)d_in[11];
    const float* b2       = (const float*)d_in[12];
    const float* bn_g     = (const float*)d_in[13];
    const float* bn_b     = (const float*)d_in[14];

    int N = in_sizes[0] / 9;
    int E = in_sizes[1] / 2;
    float invN = 1.0f / (float)N;

    static bool inited = false;
    if (!inited) {
        cudaFuncSetAttribute(gemm1_kernel, cudaFuncAttributeMaxDynamicSharedMemorySize, (int)GEMM1_SMEM);
        cudaFuncSetAttribute(gemm2_kernel, cudaFuncAttributeMaxDynamicSharedMemorySize, (int)GEMM2_SMEM);
        inited = true;
    }

    int nodeBlocks = (N * 16 + 255) / 256;
    int rowBlocks  = (N + 127) / 128;
    int eBlocks    = (E + 255) / 256;
    int scanBlocks = (N + 511) / 512;
    int aggBlocks  = (N + 15) / 16;

    atom_kernel<<<nodeBlocks, 256>>>(x, atom_emb, N);
    init_aff_kernel<<<1, 128>>>();
    hist_kernel<<<eBlocks, 256>>>(ei, E);
    scanA_kernel<<<scanBlocks, 512>>>(N);
    scanB_kernel<<<1, 512>>>(scanBlocks);
    scanC_kernel<<<scanBlocks, 512>>>(N, E);
    scatter_kernel<<<eBlocks, 256>>>(ei, ea, E);

    for (int l = 0; l < NLAYER; ++l) {
        agg_kernel<<<aggBlocks, 256>>>(bond_emb + (size_t)l * 3 * 8 * 64, (l > 0) ? 1 : 0, N);
        gemm1_kernel<<<rowBlocks, 512, GEMM1_SMEM>>>((l > 0) ? 1 : 0, eps + l,
                                                     W1 + (size_t)l * 64 * 128,
                                                     b1 + (size_t)l * 128, N);
        reduce1_kernel<<<1, 128>>>(bn1_g + (size_t)l * 128, bn1_b + (size_t)l * 128, invN);
        gemm2_kernel<<<rowBlocks, 512, GEMM2_SMEM>>>(W2 + (size_t)l * 128 * 64,
                                                     b2 + (size_t)l * 64, N);
        reduce2_kernel<<<1, 64>>>(bn_g + (size_t)l * 64, bn_b + (size_t)l * 64, invN);
    }

    final_kernel<<<nodeBlocks, 256>>>(batch, (float*)d_out, N, (long long)out_size);
}

// round 16
// speedup vs baseline: 1.2015x; 1.0785x over previous
#include <cuda_runtime.h>
#include <cuda_bf16.h>

#define EMB 64
#define MAXN 100000
#define MAXE 1000000
#define NLAYER 4
#define ZS_STRIDE 132   // padded smem stride for A-tiles (16B aligned, breaks STS conflicts)

// ---------------- scratch (__device__ globals: allocation-free) ----------------
__device__ float g_h[(size_t)MAXN * 64];          // current node features (raw, pre-affine)
__device__ float g_y[(size_t)MAXN * 128];         // GEMM1 output
__device__ float g_stats[384];                    // [sum128, sq128, sum64, sq64] (BSS zero)
__device__ float g_aff1[256];                     // BN1 affine: a[128], c[128]
__device__ float g_aff2[128];                     // outer BN affine: a[64], c[64]
// CSR build scratch (all re-established every call; g_deg zeroed by scanC)
__device__ int  g_deg[MAXN];
__device__ int  g_rowptr[MAXN + 1];
__device__ int  g_part[512];
__device__ int  g_cursor[MAXN];
__device__ int2 g_edge[MAXE];                     // {src, b0|b1<<8|b2<<16}

// ---------------- f32x2 packed-FMA helpers (sm_103a) ----------------------------
__device__ __forceinline__ void ffma2(unsigned long long& d, unsigned long long a,
                                      unsigned long long b) {
    asm("fma.rn.f32x2 %0, %1, %2, %0;" : "+l"(d) : "l"(a), "l"(b));
}
__device__ __forceinline__ unsigned long long bcast2(float v) {
    unsigned long long r;
    asm("mov.b64 %0, {%1, %1};" : "=l"(r) : "f"(v));
    return r;
}
__device__ __forceinline__ float2 unpack2(unsigned long long v) {
    float2 r;
    asm("mov.b64 {%0, %1}, %2;" : "=f"(r.x), "=f"(r.y) : "l"(v));
    return r;
}

// ---------------- init affine to identity (for layer 0 consumers) --------------
__global__ void init_aff_kernel() {
    int t = threadIdx.x;
    if (t < 64) g_aff2[t] = 1.0f;
    else        g_aff2[t] = 0.0f;   // t in [64,128)
}

// ---------------- atom encoder: h[n] = sum_c atom_emb[c][x[n,c]] ----------------
__global__ void atom_kernel(const int* __restrict__ x, const float* __restrict__ aemb, int N) {
    int t = blockIdx.x * blockDim.x + threadIdx.x;
    int node = t >> 4, lane = t & 15;
    if (node >= N) return;
    float4 s = make_float4(0.f, 0.f, 0.f, 0.f);
#pragma unroll
    for (int c = 0; c < 9; c++) {
        int v = __ldg(&x[node * 9 + c]);
        float4 e = *(const float4*)&aemb[((size_t)(c * 64 + v)) * 64 + lane * 4];
        s.x += e.x; s.y += e.y; s.z += e.z; s.w += e.w;
    }
    *(float4*)&g_h[(size_t)node * 64 + lane * 4] = s;
}

// ================= CSR build (once per call; edge structure is layer-invariant) =
__global__ void hist_kernel(const int* __restrict__ ei, int E) {
    int e = blockIdx.x * blockDim.x + threadIdx.x;
    if (e < E) atomicAdd(&g_deg[__ldg(&ei[E + e])], 1);
}

__global__ __launch_bounds__(512) void scanA_kernel(int N) {
    __shared__ int s[512];
    int tx = threadIdx.x;
    int i = blockIdx.x * 512 + tx;
    int d = (i < N) ? g_deg[i] : 0;
    s[tx] = d;
    __syncthreads();
#pragma unroll
    for (int o = 1; o < 512; o <<= 1) {
        int v = (tx >= o) ? s[tx - o] : 0;
        __syncthreads();
        if (tx >= o) s[tx] += v;
        __syncthreads();
    }
    if (i < N) g_rowptr[i] = s[tx] - d;      // exclusive within block
    if (tx == 511) g_part[blockIdx.x] = s[511];
}

__global__ __launch_bounds__(512) void scanB_kernel(int nb) {
    __shared__ int s[512];
    int tx = threadIdx.x;
    int d = (tx < nb) ? g_part[tx] : 0;
    s[tx] = d;
    __syncthreads();
#pragma unroll
    for (int o = 1; o < 512; o <<= 1) {
        int v = (tx >= o) ? s[tx - o] : 0;
        __syncthreads();
        if (tx >= o) s[tx] += v;
        __syncthreads();
    }
    if (tx < nb) g_part[tx] = s[tx] - d;
}

__global__ __launch_bounds__(512) void scanC_kernel(int N, int E) {
    int i = blockIdx.x * 512 + threadIdx.x;
    if (i < N) {
        int v = g_rowptr[i] + g_part[blockIdx.x];
        g_rowptr[i] = v;
        g_cursor[i] = v;
        g_deg[i] = 0;
    }
    if (i == 0) g_rowptr[N] = E;
}

__global__ void scatter_kernel(const int* __restrict__ ei, const int* __restrict__ ea, int E) {
    int e = blockIdx.x * blockDim.x + threadIdx.x;
    if (e >= E) return;
    int src = __ldg(&ei[e]);
    int dst = __ldg(&ei[E + e]);
    int pk = __ldg(&ea[e * 3 + 0]) | (__ldg(&ea[e * 3 + 1]) << 8) | (__ldg(&ea[e * 3 + 2]) << 16);
    int pos = atomicAdd(&g_cursor[dst], 1);
    g_edge[pos] = make_int2(src, pk);
}

// ---------------- GEMM1 (fused aggregation): Y = Z @ W1 + b1; stats(Y) ----------
// Z[r] = (1+eps)*heff(r) + sum_{e in CSR[r]} relu(heff(src)+ee)  computed in-staging.
// block tile 128x128, K=64, 512 threads.
// Staging: 32 groups x 16 lanes; each group walks 4 rows' CSR ranges.
// Mainloop: 2-D warp grid 4x4, warp tile 32x32 (rl=lane&7 rows, cl=lane>>3 cols).
#define GEMM1_SMEM ((64 * ZS_STRIDE + 64 * 128 + 256 + 1536) * sizeof(float))
__global__ __launch_bounds__(512, 2) void gemm1_kernel(int doRelu, const float* __restrict__ epsp,
                                                       const float* __restrict__ W1,
                                                       const float* __restrict__ bias1,
                                                       const float* __restrict__ bt, int N) {
    extern __shared__ float sm[];
    float* Zs   = sm;                       // [k][m] 64 x ZS_STRIDE (128 used)
    float* Ws   = sm + 64 * ZS_STRIDE;      // [k][n] 64x128
    float* ssum = Ws + 64 * 128;            // [128]
    float* ssq  = ssum + 128;               // [128]
    float* sbt  = ssq + 128;                // [1536] bond embedding table
    int tid = threadIdx.x;
    int rowBase = blockIdx.x * 128;
    float ope = 1.0f + *epsp;

    for (int t = tid; t < (64 * 128) / 4; t += 512)
        ((float4*)Ws)[t] = ((const float4*)W1)[t];
    for (int t = tid; t < 1536; t += 512) sbt[t] = bt[t];
    if (tid < 128) { ssum[tid] = 0.f; ssq[tid] = 0.f; }
    __syncthreads();   // sbt ready for edge walk

    // ---- fused aggregation staging ----
    {
        int lane = tid & 15, grp = tid >> 4;
        int lane4 = lane * 4;
        float4 a4 = *(const float4*)(g_aff2 + lane4);
        float4 c4 = *(const float4*)(g_aff2 + 64 + lane4);
#pragma unroll 1
        for (int j = 0; j < 4; j++) {
            int r = grp * 4 + j;
            int grow = rowBase + r;
            float4 acc = make_float4(0.f, 0.f, 0.f, 0.f);
            if (grow < N) {
                // self term: ope * heff(row)
                float4 hv = *(const float4*)&g_h[(size_t)grow * 64 + lane4];
                float h0 = fmaf(a4.x, hv.x, c4.x);
                float h1 = fmaf(a4.y, hv.y, c4.y);
                float h2 = fmaf(a4.z, hv.z, c4.z);
                float h3 = fmaf(a4.w, hv.w, c4.w);
                if (doRelu) { h0 = fmaxf(h0, 0.f); h1 = fmaxf(h1, 0.f); h2 = fmaxf(h2, 0.f); h3 = fmaxf(h3, 0.f); }
                acc.x = ope * h0; acc.y = ope * h1; acc.z = ope * h2; acc.w = ope * h3;
                // edge walk
                int e0 = __ldg(&g_rowptr[grow]);
                int e1 = __ldg(&g_rowptr[grow + 1]);
                int2 ed;
                if (e0 < e1) ed = __ldg(&g_edge[e0]);
#pragma unroll 1
                for (int i = e0; i < e1; i++) {
                    int2 nxt;
                    if (i + 1 < e1) nxt = __ldg(&g_edge[i + 1]);   // prefetch
                    int src = ed.x;
                    int b0 = ed.y & 255, b1 = (ed.y >> 8) & 255, b2 = (ed.y >> 16) & 255;
                    float4 sv = __ldg((const float4*)&g_h[(size_t)src * 64 + lane4]);
                    float4 e0v = *(float4*)&sbt[(0 * 8 + b0) * 64 + lane4];
                    float4 e1v = *(float4*)&sbt[(1 * 8 + b1) * 64 + lane4];
                    float4 e2v = *(float4*)&sbt[(2 * 8 + b2) * 64 + lane4];
                    float s0 = fmaf(a4.x, sv.x, c4.x);
                    float s1 = fmaf(a4.y, sv.y, c4.y);
                    float s2 = fmaf(a4.z, sv.z, c4.z);
                    float s3 = fmaf(a4.w, sv.w, c4.w);
                    if (doRelu) { s0 = fmaxf(s0, 0.f); s1 = fmaxf(s1, 0.f); s2 = fmaxf(s2, 0.f); s3 = fmaxf(s3, 0.f); }
                    acc.x += fmaxf(s0 + e0v.x + e1v.x + e2v.x, 0.f);
                    acc.y += fmaxf(s1 + e0v.y + e1v.y + e2v.y, 0.f);
                    acc.z += fmaxf(s2 + e0v.z + e1v.z + e2v.z, 0.f);
                    acc.w += fmaxf(s3 + e0v.w + e1v.w + e2v.w, 0.f);
                    ed = nxt;
                }
            }
            Zs[(lane4 + 0) * ZS_STRIDE + r] = acc.x;
            Zs[(lane4 + 1) * ZS_STRIDE + r] = acc.y;
            Zs[(lane4 + 2) * ZS_STRIDE + r] = acc.z;
            Zs[(lane4 + 3) * ZS_STRIDE + r] = acc.w;
        }
    }
    __syncthreads();

    int lane = tid & 31, wid = tid >> 5;
    int warpR = wid & 3, warpC = wid >> 2;
    int rl = lane & 7, cl = lane >> 3;
    int rowOff = warpR * 32 + rl * 4;   // 4 rows (2 f32x2 pairs)
    int colOff = warpC * 32 + cl * 8;   // 8 cols

    unsigned long long acc2[2][8];
#pragma unroll
    for (int i = 0; i < 2; i++)
#pragma unroll
        for (int j = 0; j < 8; j++) acc2[i][j] = 0ull;

#pragma unroll 4
    for (int k = 0; k < 64; ++k) {
        ulonglong2 ap = *(ulonglong2*)(Zs + k * ZS_STRIDE + rowOff);
        float4 bv0 = *(float4*)(Ws + k * 128 + colOff);
        float4 bv1 = *(float4*)(Ws + k * 128 + colOff + 4);
        {
            unsigned long long b0 = bcast2(bv0.x), b1 = bcast2(bv0.y),
                               b2 = bcast2(bv0.z), b3 = bcast2(bv0.w);
            ffma2(acc2[0][0], ap.x, b0); ffma2(acc2[1][0], ap.y, b0);
            ffma2(acc2[0][1], ap.x, b1); ffma2(acc2[1][1], ap.y, b1);
            ffma2(acc2[0][2], ap.x, b2); ffma2(acc2[1][2], ap.y, b2);
            ffma2(acc2[0][3], ap.x, b3); ffma2(acc2[1][3], ap.y, b3);
        }
        {
            unsigned long long b4 = bcast2(bv1.x), b5 = bcast2(bv1.y),
                               b6 = bcast2(bv1.z), b7 = bcast2(bv1.w);
            ffma2(acc2[0][4], ap.x, b4); ffma2(acc2[1][4], ap.y, b4);
            ffma2(acc2[0][5], ap.x, b5); ffma2(acc2[1][5], ap.y, b5);
            ffma2(acc2[0][6], ap.x, b6); ffma2(acc2[1][6], ap.y, b6);
            ffma2(acc2[0][7], ap.x, b7); ffma2(acc2[1][7], ap.y, b7);
        }
    }

    float4 bb0 = *(const float4*)(bias1 + colOff);
    float4 bb1 = *(const float4*)(bias1 + colOff + 4);
    float bj[8] = {bb0.x, bb0.y, bb0.z, bb0.w, bb1.x, bb1.y, bb1.z, bb1.w};
    float csum[8] = {0, 0, 0, 0, 0, 0, 0, 0}, csq[8] = {0, 0, 0, 0, 0, 0, 0, 0};
#pragma unroll
    for (int ip = 0; ip < 2; ip++) {
#pragma unroll
        for (int half = 0; half < 2; half++) {
            int grow = rowBase + rowOff + ip * 2 + half;
            if (grow < N) {
                float y[8];
#pragma unroll
                for (int j = 0; j < 8; j++) {
                    float2 p = unpack2(acc2[ip][j]);
                    float v = (half == 0 ? p.x : p.y) + bj[j];
                    y[j] = v;
                    csum[j] += v;
                    csq[j]  += v * v;
                }
                float* yp = g_y + (size_t)grow * 128 + colOff;
                *(float4*)yp       = make_float4(y[0], y[1], y[2], y[3]);
                *(float4*)(yp + 4) = make_float4(y[4], y[5], y[6], y[7]);
            }
        }
    }
    // segmented reduce over rl (8-lane groups share the same cols), then 1 atomic/col
#pragma unroll
    for (int j = 0; j < 8; j++) {
        float s = csum[j], q = csq[j];
        s += __shfl_xor_sync(0xffffffffu, s, 1);
        s += __shfl_xor_sync(0xffffffffu, s, 2);
        s += __shfl_xor_sync(0xffffffffu, s, 4);
        q += __shfl_xor_sync(0xffffffffu, q, 1);
        q += __shfl_xor_sync(0xffffffffu, q, 2);
        q += __shfl_xor_sync(0xffffffffu, q, 4);
        if (rl == 0) {
            atomicAdd(&ssum[colOff + j], s);
            atomicAdd(&ssq [colOff + j], q);
        }
    }
    __syncthreads();
    if (tid < 128) {
        atomicAdd(&g_stats[tid],       ssum[tid]);
        atomicAdd(&g_stats[128 + tid], ssq[tid]);
    }
}

// ---------------- reduce1: stats -> BN1 affine (a1,c1); zero consumed stats -----
__global__ void reduce1_kernel(const float* __restrict__ gam, const float* __restrict__ bet, float invN) {
    int c = threadIdx.x;   // 128
    float s = g_stats[c], sq = g_stats[128 + c];
    float m = s * invN;
    float v = sq * invN - m * m;
    float r = rsqrtf(v + 1e-5f);
    float a = gam[c] * r;
    g_aff1[c]       = a;
    g_aff1[128 + c] = bet[c] - m * a;
    g_stats[c] = 0.f;
    g_stats[128 + c] = 0.f;
}

// ---------------- GEMM2: T = relu(aff1(Y)) @ W2 + b2; stats(T); T -> g_h --------
// block tile 128x64, K=128 in 2 chunks of 64. 512 threads.
// 2-D warp grid: 8 row-warps x 2 col-warps, warp tile 16x32.
#define GEMM2_SMEM ((64 * ZS_STRIDE + 64 * 64 + 128) * sizeof(float))
__global__ __launch_bounds__(512, 2) void gemm2_kernel(const float* __restrict__ W2,
                                                       const float* __restrict__ bias2, int N) {
    extern __shared__ float sm[];
    float* Ys   = sm;                      // [k][m] 64 x ZS_STRIDE (per chunk)
    float* Ws2  = sm + 64 * ZS_STRIDE;     // [k][n] 64x64
    float* ssum = Ws2 + 64 * 64;           // [64]
    float* ssq  = ssum + 64;               // [64]
    int tid = threadIdx.x;
    int rowBase = blockIdx.x * 128;

    int lane = tid & 31, wid = tid >> 5;
    int warpR = wid & 7, warpC = wid >> 3;
    int rl = lane & 3, cl = lane >> 2;
    int rowOff = warpR * 16 + rl * 4;   // 4 rows
    int colOff = warpC * 32 + cl * 4;   // 4 cols

    if (tid < 64) { ssum[tid] = 0.f; ssq[tid] = 0.f; }

    unsigned long long acc2[2][4];
#pragma unroll
    for (int i = 0; i < 2; i++)
#pragma unroll
        for (int j = 0; j < 4; j++) acc2[i][j] = 0ull;

#pragma unroll 1
    for (int kc = 0; kc < 2; ++kc) {
        if (kc) __syncthreads();   // protect smem reuse across chunks
        for (int t = tid; t < (64 * 64) / 4; t += 512)
            ((float4*)Ws2)[t] = ((const float4*)(W2 + kc * 64 * 64))[t];
        for (int t = tid; t < 128 * 8; t += 512) {
            int r = t >> 3, kq8 = t & 7;
            int grow = rowBase + r;
#pragma unroll
            for (int hh = 0; hh < 2; hh++) {
                int kq = kq8 + hh * 8;
                float4 yv = (grow < N) ? ((const float4*)(g_y + (size_t)grow * 128))[kc * 16 + kq]
                                       : make_float4(0.f, 0.f, 0.f, 0.f);
                int kb = kc * 64 + kq * 4;
                float4 a4 = *(const float4*)(g_aff1 + kb);
                float4 c4 = *(const float4*)(g_aff1 + 128 + kb);
                Ys[(kq * 4 + 0) * ZS_STRIDE + r] = fmaxf(fmaf(a4.x, yv.x, c4.x), 0.f);
                Ys[(kq * 4 + 1) * ZS_STRIDE + r] = fmaxf(fmaf(a4.y, yv.y, c4.y), 0.f);
                Ys[(kq * 4 + 2) * ZS_STRIDE + r] = fmaxf(fmaf(a4.z, yv.z, c4.z), 0.f);
                Ys[(kq * 4 + 3) * ZS_STRIDE + r] = fmaxf(fmaf(a4.w, yv.w, c4.w), 0.f);
            }
        }
        __syncthreads();
#pragma unroll 4
        for (int k = 0; k < 64; ++k) {
            ulonglong2 ap = *(ulonglong2*)(Ys + k * ZS_STRIDE + rowOff);
            float4 bv = *(float4*)(Ws2 + k * 64 + colOff);
            unsigned long long b0 = bcast2(bv.x), b1 = bcast2(bv.y),
                               b2 = bcast2(bv.z), b3 = bcast2(bv.w);
            ffma2(acc2[0][0], ap.x, b0); ffma2(acc2[1][0], ap.y, b0);
            ffma2(acc2[0][1], ap.x, b1); ffma2(acc2[1][1], ap.y, b1);
            ffma2(acc2[0][2], ap.x, b2); ffma2(acc2[1][2], ap.y, b2);
            ffma2(acc2[0][3], ap.x, b3); ffma2(acc2[1][3], ap.y, b3);
        }
    }

    float4 bbv = *(const float4*)(bias2 + colOff);
    float bj[4] = {bbv.x, bbv.y, bbv.z, bbv.w};
    float csum[4] = {0, 0, 0, 0}, csq[4] = {0, 0, 0, 0};
#pragma unroll
    for (int ip = 0; ip < 2; ip++) {
#pragma unroll
        for (int half = 0; half < 2; half++) {
            int grow = rowBase + rowOff + ip * 2 + half;
            if (grow < N) {
                float tv[4];
#pragma unroll
                for (int j = 0; j < 4; j++) {
                    float2 p = unpack2(acc2[ip][j]);
                    float v = (half == 0 ? p.x : p.y) + bj[j];
                    tv[j] = v;
                    csum[j] += v;
                    csq[j]  += v * v;
                }
                *(float4*)(g_h + (size_t)grow * 64 + colOff) = make_float4(tv[0], tv[1], tv[2], tv[3]);
            }
        }
    }
    // segmented reduce over rl (4-lane groups share cols), then 1 atomic/col
#pragma unroll
    for (int j = 0; j < 4; j++) {
        float s = csum[j], q = csq[j];
        s += __shfl_xor_sync(0xffffffffu, s, 1);
        s += __shfl_xor_sync(0xffffffffu, s, 2);
        q += __shfl_xor_sync(0xffffffffu, q, 1);
        q += __shfl_xor_sync(0xffffffffu, q, 2);
        if (rl == 0) {
            atomicAdd(&ssum[colOff + j], s);
            atomicAdd(&ssq [colOff + j], q);
        }
    }
    __syncthreads();
    if (tid < 64) {
        atomicAdd(&g_stats[256 + tid], ssum[tid]);
        atomicAdd(&g_stats[320 + tid], ssq[tid]);
    }
}

// ---------------- reduce2: stats -> outer BN affine (a2,c2); zero stats ---------
__global__ void reduce2_kernel(const float* __restrict__ gam, const float* __restrict__ bet, float invN) {
    int c = threadIdx.x;   // 64
    float s = g_stats[256 + c], sq = g_stats[320 + c];
    float m = s * invN;
    float v = sq * invN - m * m;
    float r = rsqrtf(v + 1e-5f);
    float a = gam[c] * r;
    g_aff2[c]      = a;
    g_aff2[64 + c] = bet[c] - m * a;
    g_stats[256 + c] = 0.f;
    g_stats[320 + c] = 0.f;
}

// ---------------- final: out = aff2(g_h) (no relu) ; append batch ---------------
__global__ void final_kernel(const int* __restrict__ batch, float* __restrict__ out,
                             int N, long long outn) {
    int t = blockIdx.x * blockDim.x + threadIdx.x;
    int node = t >> 4, lane = t & 15;
    if (node < N) {
        float4 a4 = *(const float4*)(g_aff2 + lane * 4);
        float4 c4 = *(const float4*)(g_aff2 + 64 + lane * 4);
        float4 tv = *(const float4*)(g_h + (size_t)node * 64 + lane * 4);
        float4 o;
        o.x = fmaf(a4.x, tv.x, c4.x);
        o.y = fmaf(a4.y, tv.y, c4.y);
        o.z = fmaf(a4.z, tv.z, c4.z);
        o.w = fmaf(a4.w, tv.w, c4.w);
        *(float4*)(out + (size_t)node * 64 + lane * 4) = o;
    }
    if (t < N && outn >= (long long)N * 64 + N)
        out[(size_t)N * 64 + t] = (float)batch[t];
}

// -------------------------------- host side ------------------------------------
extern "C" void kernel_launch(void* const* d_in, const int* in_sizes, int n_in,
                              void* d_out, int out_size) {
    const int*   x        = (const int*)d_in[0];
    const int*   ei       = (const int*)d_in[1];
    const int*   ea       = (const int*)d_in[2];
    const int*   batch    = (const int*)d_in[3];
    const float* atom_emb = (const float*)d_in[4];
    const float* bond_emb = (const float*)d_in[5];
    const float* eps      = (const float*)d_in[6];
    const float* W1       = (const float*)d_in[7];
    const float* b1       = (const float*)d_in[8];
    const float* bn1_g    = (const float*)d_in[9];
    const float* bn1_b    = (const float*)d_in[10];
    const float* W2       = (const float*)d_in[11];
    const float* b2       = (const float*)d_in[12];
    const float* bn_g     = (const float*)d_in[13];
    const float* bn_b     = (const float*)d_in[14];

    int N = in_sizes[0] / 9;
    int E = in_sizes[1] / 2;
    float invN = 1.0f / (float)N;

    static bool inited = false;
    if (!inited) {
        cudaFuncSetAttribute(gemm1_kernel, cudaFuncAttributeMaxDynamicSharedMemorySize, (int)GEMM1_SMEM);
        cudaFuncSetAttribute(gemm2_kernel, cudaFuncAttributeMaxDynamicSharedMemorySize, (int)GEMM2_SMEM);
        inited = true;
    }

    int nodeBlocks = (N * 16 + 255) / 256;
    int rowBlocks  = (N + 127) / 128;
    int eBlocks    = (E + 255) / 256;
    int scanBlocks = (N + 511) / 512;

    atom_kernel<<<nodeBlocks, 256>>>(x, atom_emb, N);
    init_aff_kernel<<<1, 128>>>();
    hist_kernel<<<eBlocks, 256>>>(ei, E);
    scanA_kernel<<<scanBlocks, 512>>>(N);
    scanB_kernel<<<1, 512>>>(scanBlocks);
    scanC_kernel<<<scanBlocks, 512>>>(N, E);
    scatter_kernel<<<eBlocks, 256>>>(ei, ea, E);

    for (int l = 0; l < NLAYER; ++l) {
        gemm1_kernel<<<rowBlocks, 512, GEMM1_SMEM>>>((l > 0) ? 1 : 0, eps + l,
                                                     W1 + (size_t)l * 64 * 128,
                                                     b1 + (size_t)l * 128,
                                                     bond_emb + (size_t)l * 3 * 8 * 64, N);
        reduce1_kernel<<<1, 128>>>(bn1_g + (size_t)l * 128, bn1_b + (size_t)l * 128, invN);
        gemm2_kernel<<<rowBlocks, 512, GEMM2_SMEM>>>(W2 + (size_t)l * 128 * 64,
                                                     b2 + (size_t)l * 64, N);
        reduce2_kernel<<<1, 64>>>(bn_g + (size_t)l * 64, bn_b + (size_t)l * 64, invN);
    }

    final_kernel<<<nodeBlocks, 256>>>(batch, (float*)d_out, N, (long long)out_size);
}